// round 3
// baseline (speedup 1.0000x reference)
#include <cuda_runtime.h>
#include <stdint.h>
#include <math.h>
#include <algorithm>

#define Bsz 1024
#define Tt  200
#define Dd  512
#define Hh  256
#define KK  12
#define KMI 30
#define G3H 768

// JAX threefry scheme: 1 = partitionable (modern default), 0 = original.
#define THREEFRY_PARTITIONABLE 1

// ---------------- scratch ----------------------------------------------------
__device__ float g_xproj[(size_t)Tt * Bsz * G3H];  // [T][B][3H]
__device__ float g_hA[Bsz * Hh];
__device__ float g_hB[Bsz * Hh];
__device__ float g_centers[KK * Hh];
__device__ float g_hprime[KK * Hh];
__device__ int   g_codes[Bsz];

struct IdxList { int v[KK]; };

__global__ void k_init() {
    int idx = blockIdx.x * blockDim.x + threadIdx.x;
    if (idx < Bsz * Hh) g_hA[idx] = 0.0f;
}

// ---------------- x-projection GEMM: [204800,512]x[512,768] ------------------
__global__ void k_xproj(const float* __restrict__ x,
                        const float* __restrict__ w_ih,
                        const float* __restrict__ b_ih,
                        const int* __restrict__ lengths) {
    const int m0 = blockIdx.y * 128;
    const int n0 = blockIdx.x * 64;

    {   // skip block if no covered (b,t) is ever read (t >= len[b] everywhere)
        int b_first = m0 / Tt, b_last = (m0 + 127) / Tt;
        bool need = false;
        for (int b = b_first; b <= b_last && b < Bsz; b++) {
            int t_start = (m0 > b * Tt) ? (m0 - b * Tt) : 0;
            if (lengths[b] > t_start) need = true;
        }
        if (!need) return;
    }

    __shared__ float As[16][132];
    __shared__ float Bs[16][68];

    const int tid = threadIdx.x;
    const int tx = tid & 15, ty = tid >> 4;
    const int lr = tid >> 2, lc4 = tid & 3;

    float acc[8][4];
#pragma unroll
    for (int i = 0; i < 8; i++)
#pragma unroll
        for (int j = 0; j < 4; j++) acc[i][j] = 0.0f;

    for (int k0 = 0; k0 < Dd; k0 += 16) {
#pragma unroll
        for (int it = 0; it < 2; it++) {
            int r = lr + it * 64;
            float4 v = *reinterpret_cast<const float4*>(
                &x[(size_t)(m0 + r) * Dd + k0 + lc4 * 4]);
            As[lc4 * 4 + 0][r] = v.x; As[lc4 * 4 + 1][r] = v.y;
            As[lc4 * 4 + 2][r] = v.z; As[lc4 * 4 + 3][r] = v.w;
        }
        {
            float4 v = *reinterpret_cast<const float4*>(
                &w_ih[(size_t)(n0 + lr) * Dd + k0 + lc4 * 4]);
            Bs[lc4 * 4 + 0][lr] = v.x; Bs[lc4 * 4 + 1][lr] = v.y;
            Bs[lc4 * 4 + 2][lr] = v.z; Bs[lc4 * 4 + 3][lr] = v.w;
        }
        __syncthreads();
#pragma unroll
        for (int kk = 0; kk < 16; kk++) {
            float4 a0 = *reinterpret_cast<const float4*>(&As[kk][ty * 8]);
            float4 a1 = *reinterpret_cast<const float4*>(&As[kk][ty * 8 + 4]);
            float4 bv = *reinterpret_cast<const float4*>(&Bs[kk][tx * 4]);
            float a[8] = {a0.x, a0.y, a0.z, a0.w, a1.x, a1.y, a1.z, a1.w};
            float bb[4] = {bv.x, bv.y, bv.z, bv.w};
#pragma unroll
            for (int i = 0; i < 8; i++)
#pragma unroll
                for (int j = 0; j < 4; j++) acc[i][j] += a[i] * bb[j];
        }
        __syncthreads();
    }

    float4 bn = *reinterpret_cast<const float4*>(&b_ih[n0 + tx * 4]);
#pragma unroll
    for (int i = 0; i < 8; i++) {
        int m = m0 + ty * 8 + i;
        int b = m / Tt;
        int t = m - b * Tt;
        size_t base = ((size_t)t * Bsz + b) * G3H + n0 + tx * 4;
        float4 v;
        v.x = acc[i][0] + bn.x; v.y = acc[i][1] + bn.y;
        v.z = acc[i][2] + bn.z; v.w = acc[i][3] + bn.w;
        *reinterpret_cast<float4*>(&g_xproj[base]) = v;
    }
}

// ---------------- GRU step: fused 3-gate GEMM + pointwise --------------------
// Block: 64 batch rows x 32 h-cols, all 3 gates (96 GEMM cols), K=256.
__global__ void k_step(int t,
                       const float* __restrict__ w_hh,
                       const float* __restrict__ b_hh,
                       const int* __restrict__ lengths) {
    const float* __restrict__ h_in = (t & 1) ? g_hB : g_hA;
    float* __restrict__ h_out      = (t & 1) ? g_hA : g_hB;

    const int bm0 = blockIdx.y * 64;
    const int j0  = blockIdx.x * 32;

    __shared__ float Hs[16][68];
    __shared__ float Ws[16][100];

    const int tid = threadIdx.x;
    const int tx = tid & 15, ty = tid >> 4;
    const int lr = tid >> 2, lc4 = tid & 3;

    float acc[4][6];
#pragma unroll
    for (int i = 0; i < 4; i++)
#pragma unroll
        for (int j = 0; j < 6; j++) acc[i][j] = 0.0f;

    for (int k0 = 0; k0 < Hh; k0 += 16) {
        {
            float4 v = *reinterpret_cast<const float4*>(
                &h_in[(size_t)(bm0 + lr) * Hh + k0 + lc4 * 4]);
            Hs[lc4 * 4 + 0][lr] = v.x; Hs[lc4 * 4 + 1][lr] = v.y;
            Hs[lc4 * 4 + 2][lr] = v.z; Hs[lc4 * 4 + 3][lr] = v.w;
        }
#pragma unroll
        for (int it = 0; it < 6; it++) {
            int idx = tid + it * 256;   // 0..1535
            int q = idx >> 4;           // 0..95: gate*32 + jl
            int c = idx & 15;
            int g = q >> 5, jl = q & 31;
            Ws[c][q] = w_hh[(size_t)(g * Hh + j0 + jl) * Hh + k0 + c];
        }
        __syncthreads();
#pragma unroll
        for (int kk = 0; kk < 16; kk++) {
            float4 av = *reinterpret_cast<const float4*>(&Hs[kk][ty * 4]);
            float a[4] = {av.x, av.y, av.z, av.w};
            float bb[6];
#pragma unroll
            for (int g = 0; g < 3; g++) {
                bb[g * 2 + 0] = Ws[kk][g * 32 + tx * 2 + 0];
                bb[g * 2 + 1] = Ws[kk][g * 32 + tx * 2 + 1];
            }
#pragma unroll
            for (int i = 0; i < 4; i++)
#pragma unroll
                for (int j = 0; j < 6; j++) acc[i][j] += a[i] * bb[j];
        }
        __syncthreads();
    }

#pragma unroll
    for (int i = 0; i < 4; i++) {
        int b = bm0 + ty * 4 + i;
        int len = lengths[b];
#pragma unroll
        for (int jj = 0; jj < 2; jj++) {
            int col = j0 + tx * 2 + jj;
            float hr = acc[i][0 + jj] + b_hh[col];
            float hz = acc[i][2 + jj] + b_hh[Hh + col];
            float hn = acc[i][4 + jj] + b_hh[2 * Hh + col];
            size_t xb = ((size_t)t * Bsz + b) * G3H + col;
            float xr = g_xproj[xb];
            float xz = g_xproj[xb + Hh];
            float xn = g_xproj[xb + 2 * Hh];
            float r = 1.0f / (1.0f + expf(-(xr + hr)));
            float z = 1.0f / (1.0f + expf(-(xz + hz)));
            float n = tanhf(xn + r * hn);
            float hold = h_in[(size_t)b * Hh + col];
            float hnew = (1.0f - z) * n + z * hold;
            h_out[(size_t)b * Hh + col] = (t < len) ? hnew : hold;
        }
    }
}

// ---------------- kmeans -----------------------------------------------------
__global__ void k_cinit(IdxList il) {
    int d = threadIdx.x;
#pragma unroll
    for (int k = 0; k < KK; k++)
        g_centers[k * Hh + d] = g_hA[(size_t)il.v[k] * Hh + d];
}

__global__ void k_assign() {
    __shared__ float cs[KK * Hh];
    int tid = threadIdx.x;  // 128
    for (int i = tid; i < KK * Hh; i += 128) cs[i] = g_centers[i];
    __syncthreads();

    int warp = tid >> 5, lane = tid & 31;
    int b = blockIdx.x * 4 + warp;

    float dist[KK];
#pragma unroll
    for (int k = 0; k < KK; k++) dist[k] = 0.0f;
#pragma unroll
    for (int i = 0; i < 8; i++) {
        int d = lane + i * 32;
        float v = g_hA[(size_t)b * Hh + d];
#pragma unroll
        for (int k = 0; k < KK; k++) {
            float df = v - cs[k * Hh + d];
            dist[k] += df * df;
        }
    }
#pragma unroll
    for (int k = 0; k < KK; k++)
#pragma unroll
        for (int o = 16; o > 0; o >>= 1)
            dist[k] += __shfl_xor_sync(0xffffffffu, dist[k], o);

    int code = 0;
    float best = dist[0];
#pragma unroll
    for (int k = 1; k < KK; k++)
        if (dist[k] < best) { best = dist[k]; code = k; }
    if (lane == 0) g_codes[b] = code;
}

// deterministic update: one block per center, sum in ascending-b order
__global__ void k_update() {
    int k = blockIdx.x, d = threadIdx.x;
    float s = 0.0f, cnt = 0.0f;
    for (int b = 0; b < Bsz; b++) {
        if (g_codes[b] == k) { s += g_hA[(size_t)b * Hh + d]; cnt += 1.0f; }
    }
    float cold = g_centers[k * Hh + d];
    g_centers[k * Hh + d] = (cnt > 0.0f) ? (s / fmaxf(cnt, 1.0f)) : cold;
}

// ---------------- GCN (adj = I -> per-center MLP) ----------------------------
__global__ void k_hprime(const float* __restrict__ g1w, const float* __restrict__ g1b,
                         const float* __restrict__ g2w, const float* __restrict__ g2b) {
    int k = blockIdx.x, j = threadIdx.x;
    __shared__ float c[Hh], tmp[Hh];
    c[j] = g_centers[k * Hh + j];
    __syncthreads();
    float s = g1b[j];
    for (int d = 0; d < Hh; d++) s += c[d] * g1w[(size_t)d * Hh + j];
    tmp[j] = fmaxf(s, 0.0f);
    __syncthreads();
    float s2 = g2b[j];
    for (int d = 0; d < Hh; d++) s2 += tmp[d] * g2w[(size_t)d * Hh + j];
    g_hprime[k * Hh + j] = fmaxf(s2, 0.0f);
}

// ---------------- epilogue ---------------------------------------------------
__global__ void k_epi(const float* __restrict__ wt1w, const float* __restrict__ wt1b,
                      const float* __restrict__ wt2w, const float* __restrict__ wt2b,
                      float* __restrict__ out) {
    __shared__ float cs[KK * Hh], hp[KK * Hh], w1s[Hh], w2s[Hh];
    int tid = threadIdx.x;  // 128
    for (int i = tid; i < KK * Hh; i += 128) { cs[i] = g_centers[i]; hp[i] = g_hprime[i]; }
    for (int i = tid; i < Hh; i += 128)      { w1s[i] = wt1w[i]; w2s[i] = wt2w[i]; }
    __syncthreads();

    int warp = tid >> 5, lane = tid & 31;
    int b = blockIdx.x * 4 + warp;

    float e[KK];
#pragma unroll
    for (int k = 0; k < KK; k++) e[k] = 0.0f;
    float hv[8];
#pragma unroll
    for (int i = 0; i < 8; i++) {
        int d = lane + i * 32;
        float v = g_hA[(size_t)b * Hh + d];
        hv[i] = v;
#pragma unroll
        for (int k = 0; k < KK; k++) e[k] += v * cs[k * Hh + d];
    }
#pragma unroll
    for (int k = 0; k < KK; k++)
#pragma unroll
        for (int o = 16; o > 0; o >>= 1)
            e[k] += __shfl_xor_sync(0xffffffffu, e[k], o);

    float mx = 0.0f;
#pragma unroll
    for (int k = 0; k < KK; k++) { e[k] = fmaxf(e[k], 0.0f); mx = fmaxf(mx, e[k]); }
    float den = 0.0f, sc[KK];
#pragma unroll
    for (int k = 0; k < KK; k++) { sc[k] = expf(e[k] - mx); den += sc[k]; }
    float inv = 1.0f / den;
#pragma unroll
    for (int k = 0; k < KK; k++) sc[k] *= inv;

    float w1p = 0.0f, w2p = 0.0f, cl[8];
#pragma unroll
    for (int i = 0; i < 8; i++) {
        int d = lane + i * 32;
        float s = 0.0f;
#pragma unroll
        for (int k = 0; k < KK; k++) s += sc[k] * hp[k * Hh + d];
        cl[i] = s;
        w1p += s * w1s[d];
        w2p += hv[i] * w2s[d];
    }
#pragma unroll
    for (int o = 16; o > 0; o >>= 1) {
        w1p += __shfl_xor_sync(0xffffffffu, w1p, o);
        w2p += __shfl_xor_sync(0xffffffffu, w2p, o);
    }
    float w1 = 1.0f / (1.0f + expf(-(w1p + wt1b[0])));
    float w2 = 1.0f / (1.0f + expf(-(w2p + wt2b[0])));
    float w1n = w1 / (w1 + w2 + 1e-8f);
#pragma unroll
    for (int i = 0; i < 8; i++) {
        int d = lane + i * 32;
        out[(size_t)b * Hh + d] = w1n * cl[i] + (1.0f - w1n) * hv[i];
    }
}

// ---------------- host: JAX threefry replication -----------------------------
static inline uint32_t rotl32(uint32_t v, int d) { return (v << d) | (v >> (32 - d)); }

static void threefry2x32(uint32_t k0, uint32_t k1, uint32_t c0, uint32_t c1,
                         uint32_t* o0, uint32_t* o1) {
    uint32_t ks0 = k0, ks1 = k1, ks2 = k0 ^ k1 ^ 0x1BD11BDAu;
    uint32_t x0 = c0 + ks0, x1 = c1 + ks1;
    const int rA[4] = {13, 15, 26, 6};
    const int rB[4] = {17, 29, 16, 24};
#define TF4(R) for (int i_ = 0; i_ < 4; i_++) { x0 += x1; x1 = rotl32(x1, R[i_]); x1 ^= x0; }
    TF4(rA); x0 += ks1; x1 += ks2 + 1u;
    TF4(rB); x0 += ks2; x1 += ks0 + 2u;
    TF4(rA); x0 += ks0; x1 += ks1 + 3u;
    TF4(rB); x0 += ks1; x1 += ks2 + 4u;
    TF4(rA); x0 += ks2; x1 += ks0 + 5u;
#undef TF4
    *o0 = x0; *o1 = x1;
}

static void compute_init_indices(int* out12) {
    uint32_t sk0, sk1;
#if THREEFRY_PARTITIONABLE
    // split(key)[1] = full threefry output at 64-bit iota counter 1 -> (0,1)
    threefry2x32(0u, 42u, 0u, 1u, &sk0, &sk1);
#else
    // original split: counts=[0,1,2,3] halved -> subkey=(o1(0,2), o1(1,3))
    uint32_t a0, a1, b0, b1;
    threefry2x32(0u, 42u, 0u, 2u, &a0, &a1);
    threefry2x32(0u, 42u, 1u, 3u, &b0, &b1);
    sk0 = a1; sk1 = b1;
#endif
    uint32_t keys[Bsz];
#if THREEFRY_PARTITIONABLE
    // _threefry_random_bits_partitionable, bit_width=32:
    // counters (hi,lo) = (0,i); 32-bit bits = bits1 ^ bits2 (XOR of BOTH words)
    for (int i = 0; i < Bsz; i++) {
        uint32_t o0, o1;
        threefry2x32(sk0, sk1, 0u, (uint32_t)i, &o0, &o1);
        keys[i] = o0 ^ o1;
    }
#else
    for (int i = 0; i < Bsz / 2; i++) {
        uint32_t o0, o1;
        threefry2x32(sk0, sk1, (uint32_t)i, (uint32_t)(i + Bsz / 2), &o0, &o1);
        keys[i] = o0; keys[i + Bsz / 2] = o1;
    }
#endif
    int idx[Bsz];
    for (int i = 0; i < Bsz; i++) idx[i] = i;
    std::stable_sort(idx, idx + Bsz,
                     [&](int a, int b) { return keys[a] < keys[b]; });
    for (int k = 0; k < KK; k++) out12[k] = idx[k];
}

// ---------------- launch -----------------------------------------------------
extern "C" void kernel_launch(void* const* d_in, const int* in_sizes, int n_in,
                              void* d_out, int out_size) {
    const float* x       = (const float*)d_in[0];
    const int*   lengths = (const int*)  d_in[1];
    const float* w_ih    = (const float*)d_in[2];
    const float* w_hh    = (const float*)d_in[3];
    const float* b_ih    = (const float*)d_in[4];
    const float* b_hh    = (const float*)d_in[5];
    const float* g1w     = (const float*)d_in[6];
    const float* g1b     = (const float*)d_in[7];
    const float* g2w     = (const float*)d_in[8];
    const float* g2b     = (const float*)d_in[9];
    const float* wt1w    = (const float*)d_in[10];
    const float* wt1b    = (const float*)d_in[11];
    const float* wt2w    = (const float*)d_in[12];
    const float* wt2b    = (const float*)d_in[13];
    float* out = (float*)d_out;
    (void)in_sizes; (void)n_in; (void)out_size;

    IdxList il;
    compute_init_indices(il.v);

    k_init<<<1024, 256>>>();
    k_xproj<<<dim3(12, 1600), 256>>>(x, w_ih, b_ih, lengths);
    for (int t = 0; t < Tt; t++)
        k_step<<<dim3(8, 16), 256>>>(t, w_hh, b_hh, lengths);
    k_cinit<<<1, 256>>>(il);
    for (int it = 0; it < KMI; it++) {
        k_assign<<<256, 128>>>();
        k_update<<<KK, 256>>>();
    }
    k_hprime<<<KK, 256>>>(g1w, g1b, g2w, g2b);
    k_epi<<<256, 128>>>(wt1w, wt1b, wt2w, wt2b, out);
}

// round 6
// speedup vs baseline: 1.0612x; 1.0612x over previous
#include <cuda_runtime.h>
#include <stdint.h>
#include <math.h>
#include <algorithm>

#define Bsz 1024
#define Tt  200
#define Dd  512
#define Hh  256
#define KK  12
#define KMI 30
#define G3H 768
#define NSCAN 141

// ---------------- scratch ----------------------------------------------------
__device__ float g_xproj[(size_t)Tt * Bsz * G3H];  // [T][B][3H]
__device__ float g_whht[(size_t)Hh * G3H];         // [k][3H] transposed w_hh
__device__ float g_hA[Bsz * Hh];
__device__ float g_centers[KK * Hh];
__device__ float g_hprime[KK * Hh];
__device__ int   g_codes[Bsz];
__device__ int   g_order[Bsz];    // row indices sorted by length desc

struct IdxList { int v[KK]; };

__global__ void k_init() {
    int idx = blockIdx.x * blockDim.x + threadIdx.x;
    if (idx < Bsz * Hh) g_hA[idx] = 0.0f;
}

// ---------------- transpose w_hh: [3H][H] -> [H][3H] -------------------------
__global__ void k_trans(const float* __restrict__ w_hh) {
    int idx = blockIdx.x * 256 + threadIdx.x;
    if (idx < G3H * Hh) {
        int g = idx / Hh, k = idx - g * Hh;
        g_whht[(size_t)k * G3H + g] = w_hh[idx];
    }
}

// ---------------- rank-sort rows by length desc -------------------------------
__global__ void k_sort(const int* __restrict__ lengths) {
    __shared__ int ls[Bsz];
    int tid = threadIdx.x;
    for (int i = tid; i < Bsz; i += 256) ls[i] = lengths[i];
    __syncthreads();
    for (int i = tid; i < Bsz; i += 256) {
        int li = ls[i];
        int r = 0;
        for (int b = 0; b < Bsz; b++) {
            int lb = ls[b];
            r += (lb > li) || (lb == li && b < i);
        }
        g_order[r] = i;
    }
}

// ---------------- x-projection GEMM: [204800,512]x[512,768] ------------------
__global__ void k_xproj(const float* __restrict__ x,
                        const float* __restrict__ w_ih,
                        const float* __restrict__ b_ih,
                        const int* __restrict__ lengths) {
    const int m0 = blockIdx.y * 128;
    const int n0 = blockIdx.x * 64;

    {   // skip block if no covered (b,t) is ever consumed
        int b_first = m0 / Tt, b_last = (m0 + 127) / Tt;
        bool need = false;
        for (int b = b_first; b <= b_last && b < Bsz; b++) {
            int t_start = (m0 > b * Tt) ? (m0 - b * Tt) : 0;
            if (lengths[b] > t_start) need = true;
        }
        if (!need) return;
    }

    __shared__ float As[16][132];
    __shared__ float Bs[16][68];

    const int tid = threadIdx.x;
    const int tx = tid & 15, ty = tid >> 4;
    const int lr = tid >> 2, lc4 = tid & 3;

    float acc[8][4];
#pragma unroll
    for (int i = 0; i < 8; i++)
#pragma unroll
        for (int j = 0; j < 4; j++) acc[i][j] = 0.0f;

    for (int k0 = 0; k0 < Dd; k0 += 16) {
#pragma unroll
        for (int it = 0; it < 2; it++) {
            int r = lr + it * 64;
            float4 v = *reinterpret_cast<const float4*>(
                &x[(size_t)(m0 + r) * Dd + k0 + lc4 * 4]);
            As[lc4 * 4 + 0][r] = v.x; As[lc4 * 4 + 1][r] = v.y;
            As[lc4 * 4 + 2][r] = v.z; As[lc4 * 4 + 3][r] = v.w;
        }
        {
            float4 v = *reinterpret_cast<const float4*>(
                &w_ih[(size_t)(n0 + lr) * Dd + k0 + lc4 * 4]);
            Bs[lc4 * 4 + 0][lr] = v.x; Bs[lc4 * 4 + 1][lr] = v.y;
            Bs[lc4 * 4 + 2][lr] = v.z; Bs[lc4 * 4 + 3][lr] = v.w;
        }
        __syncthreads();
#pragma unroll
        for (int kk = 0; kk < 16; kk++) {
            float4 a0 = *reinterpret_cast<const float4*>(&As[kk][ty * 8]);
            float4 a1 = *reinterpret_cast<const float4*>(&As[kk][ty * 8 + 4]);
            float4 bv = *reinterpret_cast<const float4*>(&Bs[kk][tx * 4]);
            float a[8] = {a0.x, a0.y, a0.z, a0.w, a1.x, a1.y, a1.z, a1.w};
            float bb[4] = {bv.x, bv.y, bv.z, bv.w};
#pragma unroll
            for (int i = 0; i < 8; i++)
#pragma unroll
                for (int j = 0; j < 4; j++) acc[i][j] += a[i] * bb[j];
        }
        __syncthreads();
    }

    float4 bn = *reinterpret_cast<const float4*>(&b_ih[n0 + tx * 4]);
#pragma unroll
    for (int i = 0; i < 8; i++) {
        int m = m0 + ty * 8 + i;
        int b = m / Tt;
        int t = m - b * Tt;
        size_t base = ((size_t)t * Bsz + b) * G3H + n0 + tx * 4;
        float4 v;
        v.x = acc[i][0] + bn.x; v.y = acc[i][1] + bn.y;
        v.z = acc[i][2] + bn.z; v.w = acc[i][3] + bn.w;
        *reinterpret_cast<float4*>(&g_xproj[base]) = v;
    }
}

// ---------------- persistent GRU scan ----------------------------------------
// Block owns R sorted rows; h state lives in smem for all timesteps.
template <int R>
__device__ void scan_body(float (*hs)[Hh], int start,
                          const float* __restrict__ b_hh,
                          const int* __restrict__ lengths) {
    const int j = threadIdx.x;

    int rows[R], lens[R];
#pragma unroll
    for (int i = 0; i < R; i++) {
        int p = start + i;
        rows[i] = (p < Bsz) ? g_order[p] : 0;
        lens[i] = (p < Bsz) ? lengths[rows[i]] : 0;
    }
#pragma unroll
    for (int i = 0; i < R; i++) hs[i][j] = 0.0f;
    __syncthreads();

    int maxlen = 0;
#pragma unroll
    for (int i = 0; i < R; i++) maxlen = max(maxlen, lens[i]);

    const float bhr = b_hh[j], bhz = b_hh[Hh + j], bhn = b_hh[2 * Hh + j];

    for (int t = 0; t < maxlen; t++) {
        float ar[R], az[R], an[R];
#pragma unroll
        for (int i = 0; i < R; i++) { ar[i] = 0.f; az[i] = 0.f; an[i] = 0.f; }

        for (int k = 0; k < Hh; k++) {
            const float* wp = &g_whht[(size_t)k * G3H + j];
            float wr = wp[0], wz = wp[Hh], wn = wp[2 * Hh];
#pragma unroll
            for (int i = 0; i < R; i++) {
                float h = hs[i][k];
                ar[i] = fmaf(h, wr, ar[i]);
                az[i] = fmaf(h, wz, az[i]);
                an[i] = fmaf(h, wn, an[i]);
            }
        }

        float hnew[R];
#pragma unroll
        for (int i = 0; i < R; i++) {
            float hold = hs[i][j];
            if (t < lens[i]) {
                const float* xp = &g_xproj[((size_t)t * Bsz + rows[i]) * G3H + j];
                float r = 1.0f / (1.0f + expf(-(xp[0] + ar[i] + bhr)));
                float z = 1.0f / (1.0f + expf(-(xp[Hh] + az[i] + bhz)));
                // n = tanh(xn + r * hn); hn includes b_hh (bug fixed: r scales an+bhn)
                float n = tanhf(xp[2 * Hh] + r * (an[i] + bhn));
                hnew[i] = (1.0f - z) * n + z * hold;
            } else {
                hnew[i] = hold;
            }
        }
        __syncthreads();
#pragma unroll
        for (int i = 0; i < R; i++) hs[i][j] = hnew[i];
        __syncthreads();
    }

#pragma unroll
    for (int i = 0; i < R; i++)
        if (start + i < Bsz)
            g_hA[(size_t)rows[i] * Hh + j] = hs[i][j];
}

// Static schedule over sorted ranks (uniform-length order statistics):
//   bb   0..47 : R=4,  start = 4*bb           (rows    0..191)
//   bb  48..79 : R=6,  start = 192+6*(bb-48)  (rows  192..383)
//   bb  80..107: R=8,  start = 384+8*(bb-80)  (rows  384..607)
//   bb 108..127: R=11, start = 608+11*(bb-108)(rows  608..827)
//   bb 128..140: R=16, start = 828+16*(bb-128)(rows  828..1035, padded)
__global__ void __launch_bounds__(256, 1) k_scan(const float* __restrict__ b_hh,
                                                 const int* __restrict__ lengths) {
    __shared__ float hs[16][Hh];
    int bb = blockIdx.x;
    if (bb < 48)        scan_body<4>(hs, 4 * bb, b_hh, lengths);
    else if (bb < 80)   scan_body<6>(hs, 192 + 6 * (bb - 48), b_hh, lengths);
    else if (bb < 108)  scan_body<8>(hs, 384 + 8 * (bb - 80), b_hh, lengths);
    else if (bb < 128)  scan_body<11>(hs, 608 + 11 * (bb - 108), b_hh, lengths);
    else                scan_body<16>(hs, 828 + 16 * (bb - 128), b_hh, lengths);
}

// ---------------- kmeans -----------------------------------------------------
__global__ void k_cinit(IdxList il) {
    int d = threadIdx.x;
#pragma unroll
    for (int k = 0; k < KK; k++)
        g_centers[k * Hh + d] = g_hA[(size_t)il.v[k] * Hh + d];
}

__global__ void k_assign() {
    __shared__ float cs[KK * Hh];
    int tid = threadIdx.x;  // 128
    for (int i = tid; i < KK * Hh; i += 128) cs[i] = g_centers[i];
    __syncthreads();

    int warp = tid >> 5, lane = tid & 31;
    int b = blockIdx.x * 4 + warp;

    float dist[KK];
#pragma unroll
    for (int k = 0; k < KK; k++) dist[k] = 0.0f;
#pragma unroll
    for (int i = 0; i < 8; i++) {
        int d = lane + i * 32;
        float v = g_hA[(size_t)b * Hh + d];
#pragma unroll
        for (int k = 0; k < KK; k++) {
            float df = v - cs[k * Hh + d];
            dist[k] += df * df;
        }
    }
#pragma unroll
    for (int k = 0; k < KK; k++)
#pragma unroll
        for (int o = 16; o > 0; o >>= 1)
            dist[k] += __shfl_xor_sync(0xffffffffu, dist[k], o);

    int code = 0;
    float best = dist[0];
#pragma unroll
    for (int k = 1; k < KK; k++)
        if (dist[k] < best) { best = dist[k]; code = k; }
    if (lane == 0) g_codes[b] = code;
}

// deterministic update: one block per center, sum in ascending-b order
__global__ void k_update() {
    __shared__ int codes[Bsz];
    int k = blockIdx.x, d = threadIdx.x;
    for (int i = d; i < Bsz; i += 256) codes[i] = g_codes[i];
    __syncthreads();
    float s = 0.0f, cnt = 0.0f;
    for (int b = 0; b < Bsz; b++) {
        if (codes[b] == k) { s += g_hA[(size_t)b * Hh + d]; cnt += 1.0f; }
    }
    float cold = g_centers[k * Hh + d];
    g_centers[k * Hh + d] = (cnt > 0.0f) ? (s / fmaxf(cnt, 1.0f)) : cold;
}

// ---------------- GCN (adj = I -> per-center MLP) ----------------------------
__global__ void k_hprime(const float* __restrict__ g1w, const float* __restrict__ g1b,
                         const float* __restrict__ g2w, const float* __restrict__ g2b) {
    int k = blockIdx.x, j = threadIdx.x;
    __shared__ float c[Hh], tmp[Hh];
    c[j] = g_centers[k * Hh + j];
    __syncthreads();
    float s = g1b[j];
    for (int d = 0; d < Hh; d++) s += c[d] * g1w[(size_t)d * Hh + j];
    tmp[j] = fmaxf(s, 0.0f);
    __syncthreads();
    float s2 = g2b[j];
    for (int d = 0; d < Hh; d++) s2 += tmp[d] * g2w[(size_t)d * Hh + j];
    g_hprime[k * Hh + j] = fmaxf(s2, 0.0f);
}

// ---------------- epilogue ---------------------------------------------------
__global__ void k_epi(const float* __restrict__ wt1w, const float* __restrict__ wt1b,
                      const float* __restrict__ wt2w, const float* __restrict__ wt2b,
                      float* __restrict__ out) {
    __shared__ float cs[KK * Hh], hp[KK * Hh], w1s[Hh], w2s[Hh];
    int tid = threadIdx.x;  // 128
    for (int i = tid; i < KK * Hh; i += 128) { cs[i] = g_centers[i]; hp[i] = g_hprime[i]; }
    for (int i = tid; i < Hh; i += 128)      { w1s[i] = wt1w[i]; w2s[i] = wt2w[i]; }
    __syncthreads();

    int warp = tid >> 5, lane = tid & 31;
    int b = blockIdx.x * 4 + warp;

    float e[KK];
#pragma unroll
    for (int k = 0; k < KK; k++) e[k] = 0.0f;
    float hv[8];
#pragma unroll
    for (int i = 0; i < 8; i++) {
        int d = lane + i * 32;
        float v = g_hA[(size_t)b * Hh + d];
        hv[i] = v;
#pragma unroll
        for (int k = 0; k < KK; k++) e[k] += v * cs[k * Hh + d];
    }
#pragma unroll
    for (int k = 0; k < KK; k++)
#pragma unroll
        for (int o = 16; o > 0; o >>= 1)
            e[k] += __shfl_xor_sync(0xffffffffu, e[k], o);

    float mx = 0.0f;
#pragma unroll
    for (int k = 0; k < KK; k++) { e[k] = fmaxf(e[k], 0.0f); mx = fmaxf(mx, e[k]); }
    float den = 0.0f, sc[KK];
#pragma unroll
    for (int k = 0; k < KK; k++) { sc[k] = expf(e[k] - mx); den += sc[k]; }
    float inv = 1.0f / den;
#pragma unroll
    for (int k = 0; k < KK; k++) sc[k] *= inv;

    float w1p = 0.0f, w2p = 0.0f, cl[8];
#pragma unroll
    for (int i = 0; i < 8; i++) {
        int d = lane + i * 32;
        float s = 0.0f;
#pragma unroll
        for (int k = 0; k < KK; k++) s += sc[k] * hp[k * Hh + d];
        cl[i] = s;
        w1p += s * w1s[d];
        w2p += hv[i] * w2s[d];
    }
#pragma unroll
    for (int o = 16; o > 0; o >>= 1) {
        w1p += __shfl_xor_sync(0xffffffffu, w1p, o);
        w2p += __shfl_xor_sync(0xffffffffu, w2p, o);
    }
    float w1 = 1.0f / (1.0f + expf(-(w1p + wt1b[0])));
    float w2 = 1.0f / (1.0f + expf(-(w2p + wt2b[0])));
    float w1n = w1 / (w1 + w2 + 1e-8f);
#pragma unroll
    for (int i = 0; i < 8; i++) {
        int d = lane + i * 32;
        out[(size_t)b * Hh + d] = w1n * cl[i] + (1.0f - w1n) * hv[i];
    }
}

// ---------------- host: JAX threefry replication -----------------------------
static inline uint32_t rotl32(uint32_t v, int d) { return (v << d) | (v >> (32 - d)); }

static void threefry2x32(uint32_t k0, uint32_t k1, uint32_t c0, uint32_t c1,
                         uint32_t* o0, uint32_t* o1) {
    uint32_t ks0 = k0, ks1 = k1, ks2 = k0 ^ k1 ^ 0x1BD11BDAu;
    uint32_t x0 = c0 + ks0, x1 = c1 + ks1;
    const int rA[4] = {13, 15, 26, 6};
    const int rB[4] = {17, 29, 16, 24};
#define TF4(R) for (int i_ = 0; i_ < 4; i_++) { x0 += x1; x1 = rotl32(x1, R[i_]); x1 ^= x0; }
    TF4(rA); x0 += ks1; x1 += ks2 + 1u;
    TF4(rB); x0 += ks2; x1 += ks0 + 2u;
    TF4(rA); x0 += ks0; x1 += ks1 + 3u;
    TF4(rB); x0 += ks1; x1 += ks2 + 4u;
    TF4(rA); x0 += ks2; x1 += ks0 + 5u;
#undef TF4
    *o0 = x0; *o1 = x1;
}

static void compute_init_indices(int* out12) {
    uint32_t sk0, sk1;
    // split(key(42))[1] = threefry((0,42), (0,1)), both words
    threefry2x32(0u, 42u, 0u, 1u, &sk0, &sk1);
    uint32_t keys[Bsz];
    // partitionable random_bits(32): counters (0,i); bits = o0 ^ o1
    for (int i = 0; i < Bsz; i++) {
        uint32_t o0, o1;
        threefry2x32(sk0, sk1, 0u, (uint32_t)i, &o0, &o1);
        keys[i] = o0 ^ o1;
    }
    int idx[Bsz];
    for (int i = 0; i < Bsz; i++) idx[i] = i;
    std::stable_sort(idx, idx + Bsz,
                     [&](int a, int b) { return keys[a] < keys[b]; });
    for (int k = 0; k < KK; k++) out12[k] = idx[k];
}

// ---------------- launch -----------------------------------------------------
extern "C" void kernel_launch(void* const* d_in, const int* in_sizes, int n_in,
                              void* d_out, int out_size) {
    const float* x       = (const float*)d_in[0];
    const int*   lengths = (const int*)  d_in[1];
    const float* w_ih    = (const float*)d_in[2];
    const float* w_hh    = (const float*)d_in[3];
    const float* b_ih    = (const float*)d_in[4];
    const float* b_hh    = (const float*)d_in[5];
    const float* g1w     = (const float*)d_in[6];
    const float* g1b     = (const float*)d_in[7];
    const float* g2w     = (const float*)d_in[8];
    const float* g2b     = (const float*)d_in[9];
    const float* wt1w    = (const float*)d_in[10];
    const float* wt1b    = (const float*)d_in[11];
    const float* wt2w    = (const float*)d_in[12];
    const float* wt2b    = (const float*)d_in[13];
    float* out = (float*)d_out;
    (void)in_sizes; (void)n_in; (void)out_size;

    IdxList il;
    compute_init_indices(il.v);

    k_init<<<1024, 256>>>();
    k_trans<<<(G3H * Hh + 255) / 256, 256>>>(w_hh);
    k_sort<<<1, 256>>>(lengths);
    k_xproj<<<dim3(12, 1600), 256>>>(x, w_ih, b_ih, lengths);
    k_scan<<<NSCAN, 256>>>(b_hh, lengths);
    k_cinit<<<1, 256>>>(il);
    for (int it = 0; it < KMI; it++) {
        k_assign<<<256, 128>>>();
        k_update<<<KK, 256>>>();
    }
    k_hprime<<<KK, 256>>>(g1w, g1b, g2w, g2b);
    k_epi<<<256, 128>>>(wt1w, wt1b, wt2w, wt2b, out);
}